// round 5
// baseline (speedup 1.0000x reference)
#include <cuda_runtime.h>
#include <cuda_fp16.h>
#include <cstdint>

#define NB      256          // N_RES * EXPR flattened rows
#define NC      1025         // coeffs per row
#define NF      128          // frames
#define HOP     1024
#define NSAMP   131072
#define FPB     16           // frames per ifft block
#define NCHUNK  (NF / FPB)   // 8 ifft blocks per row
#define SPEC_PER_ROW 5       // 5 blocks x 205 bins = 1025 bins
#define BINS_PER_BLK 205
#define SPEC_BLOCKS  (SPEC_PER_ROW * NB)   // 1280
#define IFFT_BLOCKS  (NCHUNK * NB)         // 2048

// Scratch (allowed: __device__ globals, no runtime alloc)
__device__ __half2 g_spec[33587200];       // NB*NF*NC fp16 spectrum, 134MB
__device__ unsigned int g_row_cnt[NB];     // per-row spec completion counters

// ---------------------------------------------------------------------------
// Threefry-2x32 (20 rounds), JAX partitionable counter mode: key=(0,42),
// x=(0, i), output = v0 ^ v1.   (bit-verified in round 2)
// ---------------------------------------------------------------------------
__device__ __forceinline__ uint32_t threefry_xor(uint32_t x0, uint32_t x1) {
    const uint32_t ks0 = 0u, ks1 = 42u;
    const uint32_t ks2 = ks0 ^ ks1 ^ 0x1BD11BDAu;
    x0 += ks0; x1 += ks1;
#define TF_R(r) { x0 += x1; x1 = __funnelshift_l(x1, x1, (r)); x1 ^= x0; }
    TF_R(13) TF_R(15) TF_R(26) TF_R(6)
    x0 += ks1; x1 += ks2 + 1u;
    TF_R(17) TF_R(29) TF_R(16) TF_R(24)
    x0 += ks2; x1 += ks0 + 2u;
    TF_R(13) TF_R(15) TF_R(26) TF_R(6)
    x0 += ks0; x1 += ks1 + 3u;
    TF_R(17) TF_R(29) TF_R(16) TF_R(24)
    x0 += ks1; x1 += ks2 + 4u;
    TF_R(13) TF_R(15) TF_R(26) TF_R(6)
    x0 += ks2; x1 += ks0 + 5u;
#undef TF_R
    return x0 ^ x1;
}

// ---------------------------------------------------------------------------
__device__ __forceinline__ float2 cadd(float2 a, float2 b){ return make_float2(a.x+b.x, a.y+b.y); }
__device__ __forceinline__ float2 csub(float2 a, float2 b){ return make_float2(a.x-b.x, a.y-b.y); }
__device__ __forceinline__ float2 cmul(float2 a, float2 b){
    return make_float2(a.x*b.x - a.y*b.y, a.x*b.y + a.y*b.x);
}
#define PADI(i) ((i) + ((i) >> 5))

__device__ __forceinline__ void radix4_inv(float2 a, float2 b, float2 c, float2 d,
                                           float2& t0, float2& t1, float2& t2, float2& t3)
{
    float2 apc = cadd(a, c), amc = csub(a, c);
    float2 bpd = cadd(b, d), bmd = csub(b, d);
    t0 = cadd(apc, bpd);
    t2 = csub(apc, bpd);
    t1 = make_float2(amc.x - bmd.y, amc.y + bmd.x);  // (a-c) + i(b-d)
    t3 = make_float2(amc.x + bmd.y, amc.y - bmd.x);  // (a-c) - i(b-d)
}

// ---------------------------------------------------------------------------
__global__ void init_kernel()
{
    if (threadIdx.x < NB) g_row_cnt[threadIdx.x] = 0u;
}

// ---------------------------------------------------------------------------
// Heterogeneous fused kernel.
//   blocks [0, SPEC_BLOCKS): spectrum synthesis (ALU/MUFU-heavy)
//   blocks [SPEC_BLOCKS, +IFFT_BLOCKS): irfft + overlap-add (LDS/FMA-heavy)
// Spec blocks come first in dispatch order; ifft blocks spin on their row's
// counter, so both phases co-execute on complementary pipes.
// ---------------------------------------------------------------------------
__global__ void __launch_bounds__(256) fused_kernel(
    const float* __restrict__ amp,   const float* __restrict__ phase,
    const float* __restrict__ decay, const float* __restrict__ dith,
    float2* __restrict__ out2)
{
    __shared__ float2 bufA[1056];
    __shared__ float2 bufB[1056];

    const int tid = threadIdx.x;

    if (blockIdx.x < SPEC_BLOCKS) {
        // ================= SPEC PART =================
        const int b = blockIdx.x / SPEC_PER_ROW;
        const int c = blockIdx.x - b * SPEC_PER_ROW;
        const int k = c * BINS_PER_BLK + tid;

        if (tid < BINS_PER_BLK) {
            // inputs are (N_RES, NC, EXPR); flattened row b = r*4+e
            int pidx = (((b >> 2) * NC + k) << 2) + (b & 3);
            float a  = amp[pidx];
            float ph = phase[pidx];
            float dc = decay[pidx];
            float dt = dith[pidx];

            float sig = 1.0f / (1.0f + expf(-dc));
            float cc  = 0.5f + (sig * 0.5f) * 0.99f;
            float m   = a * a;
            float sp  = tanhf(ph) * 3.14159274101257324f;
            float d   = tanhf(dt);

            uint32_t idx = (uint32_t)(b * NF) * (uint32_t)NC + (uint32_t)k;
            float acc = 0.0f;
            __half2* __restrict__ outp = g_spec + idx;

            #pragma unroll 4
            for (int t = 0; t < NF; t++) {
                uint32_t bits = threefry_xor(0u, idx);
                float u  = __uint_as_float((bits >> 9) | 0x3f800000u) - 1.0f;
                float nz = fmaxf(-1.0f, fmaf(u, 2.0f, -1.0f));
                acc += fmaf(d, nz, sp);
                m   *= cc;

                float kq  = rintf(acc * 0.15915494309189535f);
                float red = fmaf(kq, -6.2831854820251465f, acc);
                red       = fmaf(kq,  1.7484555e-07f, red);
                float sn, cs;
                __sincosf(red, &sn, &cs);

                *outp = __floats2half2_rn(m * cs, m * sn);
                outp += NC;
                idx  += NC;
            }
        }
        // publish: all writes -> fence -> barrier -> one release increment
        __threadfence();
        __syncthreads();
        if (tid == 0) atomicAdd(&g_row_cnt[b], 1u);
        return;
    }

    // ================= IFFT + OLA PART =================
    const int id      = blockIdx.x - SPEC_BLOCKS;
    const int b       = id >> 3;              // NCHUNK == 8
    const int chunk   = id & 7;
    const int t_start = chunk * FPB;
    const int t_first = (chunk == 0) ? 0 : t_start - 1;

    // wait until all 5 spec blocks of row b have published
    if (tid == 0) {
        const volatile unsigned int* vc = g_row_cnt;
        while (vc[b] < (unsigned)SPEC_PER_ROW) __nanosleep(128);
    }
    __syncthreads();
    __threadfence();   // acquire: order spec reads after counter observation

    // ---- hoisted, frame-invariant twiddles (tid-only) ----
    float2 fw[4];
    #pragma unroll
    for (int i = 0; i < 4; i++) {
        float sw, cw;
        __sincosf((float)(tid + i * 256) * (3.14159265358979f / 1024.0f), &sw, &cw);
        fw[i] = make_float2(cw, sw);
    }
    const float2 s0w1 = cmul(fw[0], fw[0]);
    float2 stw1[3];
    #pragma unroll
    for (int s = 1; s < 4; s++) {
        int p = tid >> (2 * s);
        float n = (float)(1024 >> (2 * s));
        float sn, cs;
        __sincosf((float)p * (6.283185307179586f / n), &sn, &cs);
        stw1[s - 1] = make_float2(cs, sn);
    }

    float2 prev2 = make_float2(0.0f, 0.0f);
    float2 prev3 = make_float2(0.0f, 0.0f);

    for (int t = t_first; t < t_start + FPB; t++) {
        const __half2* __restrict__ X = g_spec + (size_t)(b * NF + t) * NC;

        // Hermitian fold -> Z[k] = A + iB (1/2048 normalization folded in)
        float2 z[4];
        const float inv = 1.0f / 2048.0f;
        #pragma unroll
        for (int i = 0; i < 4; i++) {
            int k = tid + i * 256;
            float2 Xk = __half22float2(X[k]);
            float2 Xm = __half22float2(X[1024 - k]);
            if (k == 0) { Xk.y = 0.0f; Xm.y = 0.0f; }
            float Ax = (Xk.x + Xm.x) * inv;
            float Ay = (Xk.y - Xm.y) * inv;
            float Dx = (Xk.x - Xm.x) * inv;
            float Dy = (Xk.y + Xm.y) * inv;
            float Bx = Dx * fw[i].x - Dy * fw[i].y;
            float By = Dx * fw[i].y + Dy * fw[i].x;
            z[i] = make_float2(Ax - By, Ay + Bx);
        }

        // Stage 0 (s=1) in registers
        {
            float2 r0, r1, r2, r3;
            radix4_inv(z[0], z[1], z[2], z[3], r0, r1, r2, r3);
            float2 w2 = cmul(s0w1, s0w1);
            float2 w3 = cmul(w2, s0w1);
            int wb = tid << 2;
            bufA[PADI(wb)]     = r0;
            bufA[PADI(wb + 1)] = cmul(r1, s0w1);
            bufA[PADI(wb + 2)] = cmul(r2, w2);
            bufA[PADI(wb + 3)] = cmul(r3, w3);
        }
        __syncthreads();

        // Stages 1..3 via shared memory (s = 4, 16, 64)
        float2* src = bufA;
        float2* dst = bufB;
        #pragma unroll
        for (int stage = 1; stage < 4; stage++) {
            const int ls = 2 * stage;
            const int s_ = 1 << ls;
            const int q  = tid & (s_ - 1);
            const int p  = tid >> ls;

            float2 a  = src[PADI(tid)];
            float2 bb = src[PADI(tid + 256)];
            float2 c  = src[PADI(tid + 512)];
            float2 d  = src[PADI(tid + 768)];

            float2 r0, r1, r2, r3;
            radix4_inv(a, bb, c, d, r0, r1, r2, r3);

            float2 w1 = stw1[stage - 1];
            float2 w2 = cmul(w1, w1);
            float2 w3 = cmul(w2, w1);

            int wb = q + (p << (ls + 2));
            dst[PADI(wb)]        = r0;
            dst[PADI(wb + s_)]   = cmul(r1, w1);
            dst[PADI(wb + 2*s_)] = cmul(r2, w2);
            dst[PADI(wb + 3*s_)] = cmul(r3, w3);
            __syncthreads();
            float2* tmp = src; src = dst; dst = tmp;
        }

        // Stage 4 (s=256, p=0, twiddle=1) fused epilogue + OLA output
        {
            float2 a  = src[PADI(tid)];
            float2 bb = src[PADI(tid + 256)];
            float2 c  = src[PADI(tid + 512)];
            float2 d  = src[PADI(tid + 768)];
            float2 r0, r1, r2, r3;
            radix4_inv(a, bb, c, d, r0, r1, r2, r3);

            if (t >= t_start) {
                int base = b * (NSAMP / 2) + t * 512;
                out2[base + tid]       = make_float2(r0.x + prev2.x, r0.y + prev2.y);
                out2[base + 256 + tid] = make_float2(r1.x + prev3.x, r1.y + prev3.y);
            }
            prev2 = r2;
            prev3 = r3;
        }
        // bufA reuse in next prologue is ordered by the last stage's sync;
        // epilogue's bufB reads are ordered before the next stage-1 writes
        // by the sync following the next prologue.
    }
}

// ---------------------------------------------------------------------------
extern "C" void kernel_launch(void* const* d_in, const int* in_sizes, int n_in,
                              void* d_out, int out_size)
{
    const float* amp   = (const float*)d_in[0];
    const float* phase = (const float*)d_in[1];
    const float* decay = (const float*)d_in[2];
    const float* dith  = (const float*)d_in[3];
    float* out = (float*)d_out;

    init_kernel<<<1, 256>>>();
    fused_kernel<<<SPEC_BLOCKS + IFFT_BLOCKS, 256>>>(amp, phase, decay, dith,
                                                     (float2*)out);
}

// round 6
// speedup vs baseline: 1.3035x; 1.3035x over previous
#include <cuda_runtime.h>
#include <cuda_fp16.h>
#include <cstdint>

#define NB      256          // N_RES * EXPR flattened rows
#define NC      1025         // coeffs per row
#define NF      128          // frames
#define HOP     1024
#define NSAMP   131072
#define FPB     16           // frames per ifft block
#define NCHUNK  (NF / FPB)   // 8

// Scratch (allowed: __device__ globals, no runtime alloc)
__device__ __half2 g_spec[33587200];     // NB*NF*NC fp16 spectrum, 134MB

// ---------------------------------------------------------------------------
// Threefry-2x32 (20 rounds), JAX partitionable counter mode: key=(0,42),
// x=(0, i), output = v0 ^ v1.   (bit-verified in round 2)
// ---------------------------------------------------------------------------
__device__ __forceinline__ uint32_t threefry_xor(uint32_t x0, uint32_t x1) {
    const uint32_t ks0 = 0u, ks1 = 42u;
    const uint32_t ks2 = ks0 ^ ks1 ^ 0x1BD11BDAu;
    x0 += ks0; x1 += ks1;
#define TF_R(r) { x0 += x1; x1 = __funnelshift_l(x1, x1, (r)); x1 ^= x0; }
    TF_R(13) TF_R(15) TF_R(26) TF_R(6)
    x0 += ks1; x1 += ks2 + 1u;
    TF_R(17) TF_R(29) TF_R(16) TF_R(24)
    x0 += ks2; x1 += ks0 + 2u;
    TF_R(13) TF_R(15) TF_R(26) TF_R(6)
    x0 += ks0; x1 += ks1 + 3u;
    TF_R(17) TF_R(29) TF_R(16) TF_R(24)
    x0 += ks1; x1 += ks2 + 4u;
    TF_R(13) TF_R(15) TF_R(26) TF_R(6)
    x0 += ks2; x1 += ks0 + 5u;
#undef TF_R
    return x0 ^ x1;
}

// ---------------------------------------------------------------------------
// Kernel 1: spectrum synthesis (unchanged structure; fmax removed — 2u-1 >= -1
// always holds for u in [0,1), so the clamp is a no-op).
// ---------------------------------------------------------------------------
__global__ void __launch_bounds__(256) spec_kernel(
    const float* __restrict__ amp,   const float* __restrict__ phase,
    const float* __restrict__ decay, const float* __restrict__ dith)
{
    int gid = blockIdx.x * 256 + threadIdx.x;
    if (gid >= NB * NC) return;
    int b = gid / NC;
    int k = gid - b * NC;
    int pidx = (((b >> 2) * NC + k) << 2) + (b & 3);   // (N_RES, NC, EXPR) layout

    float a  = amp[pidx];
    float ph = phase[pidx];
    float dc = decay[pidx];
    float dt = dith[pidx];

    float sig = 1.0f / (1.0f + expf(-dc));
    float c   = 0.5f + (sig * 0.5f) * 0.99f;
    float m   = a * a;
    float sp  = tanhf(ph) * 3.14159274101257324f;
    float d   = tanhf(dt);

    uint32_t idx = (uint32_t)(b * NF) * (uint32_t)NC + (uint32_t)k;
    float acc = 0.0f;
    __half2* __restrict__ outp = g_spec + idx;

    #pragma unroll 4
    for (int t = 0; t < NF; t++) {
        uint32_t bits = threefry_xor(0u, idx);
        float u  = __uint_as_float((bits >> 9) | 0x3f800000u) - 1.0f;  // [0,1)
        float nz = fmaf(u, 2.0f, -1.0f);                               // [-1,1)
        acc += fmaf(d, nz, sp);
        m   *= c;

        float kq  = rintf(acc * 0.15915494309189535f);
        float red = fmaf(kq, -6.2831854820251465f, acc);
        red       = fmaf(kq,  1.7484555e-07f, red);
        float sn, cs;
        __sincosf(red, &sn, &cs);

        *outp = __floats2half2_rn(m * cs, m * sn);
        outp += NC;
        idx  += NC;
    }
}

// ---------------------------------------------------------------------------
// complex helpers
// ---------------------------------------------------------------------------
__device__ __forceinline__ float2 cadd(float2 a, float2 b){ return make_float2(a.x+b.x, a.y+b.y); }
__device__ __forceinline__ float2 csub(float2 a, float2 b){ return make_float2(a.x-b.x, a.y-b.y); }
__device__ __forceinline__ float2 cmul(float2 a, float2 b){
    return make_float2(a.x*b.x - a.y*b.y, a.x*b.y + a.y*b.x);
}
__device__ __forceinline__ float2 cmulc(float2 a, float cx, float cy){
    return make_float2(a.x*cx - a.y*cy, a.x*cy + a.y*cx);
}

__device__ __forceinline__ void radix4_inv(float2 a, float2 b, float2 c, float2 d,
                                           float2& t0, float2& t1, float2& t2, float2& t3)
{
    float2 apc = cadd(a, c), amc = csub(a, c);
    float2 bpd = cadd(b, d), bmd = csub(b, d);
    t0 = cadd(apc, bpd);
    t2 = csub(apc, bpd);
    t1 = make_float2(amc.x - bmd.y, amc.y + bmd.x);  // (a-c) + i(b-d)
    t3 = make_float2(amc.x + bmd.y, amc.y - bmd.x);  // (a-c) - i(b-d)
}

// Inverse 16-pt DFT, natural-order in/out, via two radix-4 layers.
// Inner twiddles W16^e = e^{+2pi i e/16} (compile-time constants).
__device__ __forceinline__ void dft16_inv(const float2 v[16], float2 y[16])
{
    const float wc[10] = {1.0f, 0.9238795325f, 0.7071067812f, 0.3826834324f,
                          0.0f, 0.0f, -0.7071067812f, 0.0f, 0.0f, -0.9238795325f};
    const float ws[10] = {0.0f, 0.3826834324f, 0.7071067812f, 0.9238795325f,
                          1.0f, 0.0f,  0.7071067812f, 0.0f, 0.0f, -0.3826834324f};
    float2 B[16];
    #pragma unroll
    for (int n0 = 0; n0 < 4; n0++) {
        float2 a0, a1, a2, a3;
        radix4_inv(v[n0], v[n0+4], v[n0+8], v[n0+12], a0, a1, a2, a3);
        B[n0]      = a0;
        B[4  + n0] = (n0 == 0) ? a1 : cmulc(a1, wc[n0],     ws[n0]);
        B[8  + n0] = (n0 == 0) ? a2 : cmulc(a2, wc[2*n0],   ws[2*n0]);
        B[12 + n0] = (n0 == 0) ? a3 : cmulc(a3, wc[3*n0],   ws[3*n0]);
    }
    #pragma unroll
    for (int k0 = 0; k0 < 4; k0++) {
        float2 x0, x1, x2, x3;
        radix4_inv(B[4*k0], B[4*k0+1], B[4*k0+2], B[4*k0+3], x0, x1, x2, x3);
        y[k0] = x0; y[k0+4] = x1; y[k0+8] = x2; y[k0+12] = x3;
    }
}

// e^{i pi j/16}, j = 0..15 (fold twiddle per-j factor; folds to immediates)
__device__ __forceinline__ float2 fj_const(int j)
{
    const float fc[16] = { 1.0f, 0.9807852804f, 0.9238795325f, 0.8314696123f,
                           0.7071067812f, 0.5555702330f, 0.3826834324f, 0.1950903220f,
                           0.0f, -0.1950903220f, -0.3826834324f, -0.5555702330f,
                          -0.7071067812f, -0.8314696123f, -0.9238795325f, -0.9807852804f };
    const float fs[16] = { 0.0f, 0.1950903220f, 0.3826834324f, 0.5555702330f,
                           0.7071067812f, 0.8314696123f, 0.9238795325f, 0.9807852804f,
                           1.0f, 0.9807852804f, 0.9238795325f, 0.8314696123f,
                           0.7071067812f, 0.5555702330f, 0.3826834324f, 0.1950903220f };
    return make_float2(fc[j], fs[j]);
}

// XOR stagger: phys(L) = L ^ ((L>>4)&15) — conflict-free for all phases here.
#define STAG(L) ((L) ^ (((L) >> 4) & 15))

// ---------------------------------------------------------------------------
// Kernel 2: fused irfft + overlap-add, radix-16 formulation.
// 64 threads per block = one frame pipeline; 16 complex values per thread.
//   prologue: Hermitian fold (global, fp16) -> 16 regs (indices t + 64j)
//   round 1:  DFT16 in regs, twiddle e^{2pi i t j/1024}, write smem
//   round 2:  read (t+64j), DFT16, twiddle e^{2pi i (t>>4) j/64}, write smem
//   round 3:  4x radix-4 (stride 256, twiddle-free) + OLA, write global
// OLA overlap carried in registers across the sequential 16(+1) frame loop.
// ---------------------------------------------------------------------------
__global__ void __launch_bounds__(64) ifft_ola_kernel(float2* __restrict__ out2)
{
    __shared__ float2 buf[1024];

    const int t       = threadIdx.x;          // 0..63
    const int b       = blockIdx.y;
    const int chunk   = blockIdx.x;
    const int t_start = chunk * FPB;
    const int t_first = (chunk == 0) ? 0 : t_start - 1;

    // hoisted twiddle bases (frame-invariant)
    float sb, cb;
    __sincosf((float)t * (3.14159265358979f / 1024.0f), &sb, &cb);
    const float2 fbase = make_float2(cb, sb);          // e^{i pi t/1024}
    const float2 w1t   = cmul(fbase, fbase);           // e^{2pi i t/1024}
    const int    p2    = t >> 4;
    float s2, c2;
    __sincosf((float)p2 * (6.283185307179586f / 64.0f), &s2, &c2);
    const float2 w2t = make_float2(c2, s2);            // e^{2pi i p2/64}

    float2 prev0[4], prev1[4];
    #pragma unroll
    for (int e = 0; e < 4; e++) {
        prev0[e] = make_float2(0.0f, 0.0f);
        prev1[e] = make_float2(0.0f, 0.0f);
    }

    for (int tf = t_first; tf < t_start + FPB; tf++) {
        const __half2* __restrict__ X = g_spec + (size_t)(b * NF + tf) * NC;

        // ---- prologue: Hermitian fold (1/2048 normalization folded in) ----
        float2 v[16];
        const float inv = 1.0f / 2048.0f;
        #pragma unroll
        for (int j = 0; j < 16; j++) {
            int k = t + 64 * j;
            float2 Xk = __half22float2(X[k]);
            float2 Xm = __half22float2(X[1024 - k]);
            if (k == 0) { Xk.y = 0.0f; Xm.y = 0.0f; }
            float Ax = (Xk.x + Xm.x) * inv;
            float Ay = (Xk.y - Xm.y) * inv;
            float Dx = (Xk.x - Xm.x) * inv;
            float Dy = (Xk.y + Xm.y) * inv;
            float2 fw = cmul(fbase, fj_const(j));       // e^{i pi (t+64j)/1024}
            float Bx = Dx * fw.x - Dy * fw.y;
            float By = Dx * fw.y + Dy * fw.x;
            v[j] = make_float2(Ax - By, Ay + Bx);
        }

        // ---- round 1: radix-16 (s=1), twiddle chain e^{2pi i t j/1024} ----
        float2 y[16];
        dft16_inv(v, y);
        {
            float2 w = w1t;
            buf[STAG(16 * t)] = y[0];
            #pragma unroll
            for (int j = 1; j < 16; j++) {
                buf[STAG(16 * t + j)] = cmul(y[j], w);
                w = cmul(w, w1t);
            }
        }
        __syncthreads();

        // ---- round 2: radix-16 (s=16), in-place with read/write split ----
        #pragma unroll
        for (int j = 0; j < 16; j++) {
            int L = t + 64 * j;
            v[j] = buf[STAG(L)];
        }
        __syncthreads();
        dft16_inv(v, y);
        {
            const int base = (t & 15) + (p2 << 8);      // q + 256 p
            float2 w = w2t;
            buf[STAG(base)] = y[0];
            #pragma unroll
            for (int j = 1; j < 16; j++) {
                buf[STAG(base + 16 * j)] = cmul(y[j], w);
                w = cmul(w, w2t);
            }
        }
        __syncthreads();

        // ---- round 3: radix-4 (s=256, p=0, twiddle 1) + OLA output ----
        const int obase = b * (NSAMP / 2) + tf * 512;
        #pragma unroll
        for (int e = 0; e < 4; e++) {
            int u3 = t + 64 * e;
            int sp = u3 ^ ((u3 >> 4) & 15);             // staggered base
            float2 a  = buf[sp];
            float2 bb = buf[sp + 256];
            float2 c  = buf[sp + 512];
            float2 d  = buf[sp + 768];
            float2 r0, r1, r2, r3;
            radix4_inv(a, bb, c, d, r0, r1, r2, r3);
            // r0,r1: sample-pairs m=u3, u3+256 (first half of frame tf)
            // r2,r3: pairs m=u3+512, u3+768 (second half -> overlap for tf+1)
            if (tf >= t_start) {
                out2[obase + u3]       = make_float2(r0.x + prev0[e].x, r0.y + prev0[e].y);
                out2[obase + 256 + u3] = make_float2(r1.x + prev1[e].x, r1.y + prev1[e].y);
            }
            prev0[e] = r2;
            prev1[e] = r3;
        }
        __syncthreads();   // buf reused by next frame's round-1 writes
    }
}

// ---------------------------------------------------------------------------
extern "C" void kernel_launch(void* const* d_in, const int* in_sizes, int n_in,
                              void* d_out, int out_size)
{
    const float* amp   = (const float*)d_in[0];
    const float* phase = (const float*)d_in[1];
    const float* decay = (const float*)d_in[2];
    const float* dith  = (const float*)d_in[3];
    float* out = (float*)d_out;

    spec_kernel<<<(NB * NC + 255) / 256, 256>>>(amp, phase, decay, dith);
    dim3 grid2(NCHUNK, NB);
    ifft_ola_kernel<<<grid2, 64>>>((float2*)out);
}